// round 1
// baseline (speedup 1.0000x reference)
#include <cuda_runtime.h>
#include <math.h>

#define Bn 4
#define Cn 2
#define Tn 8
#define Hn 128
#define Wn 128
#define Nn (Tn*Hn*Wn)        // 131072
#define Dn 512
#define Pn 32
#define Fn (Cn + 3*Pn)       // 98
#define Mn 65536

#define CHUNK 8192
#define NCHUNK (Nn/CHUNK)    // 16
#define DT 128               // d-tile
#define MT 2048              // m-tile
#define SMEM_MAIN ((Tn+Hn+Wn)*DT*4)   // 135168 bytes

// scratch (no cudaMalloc allowed)
__device__ int   g_cidx[Bn*Mn];
__device__ int   g_chunk_cnt[Bn*NCHUNK];
__device__ int   g_chunk_off[Bn*NCHUNK];
__device__ float g_Et[Tn*Dn];
__device__ float g_Eh[Hn*Dn];
__device__ float g_Ew[Wn*Dn];

// ---------------- init compact index to -1 ----------------
__global__ void k_init() {
    int i = blockIdx.x * blockDim.x + threadIdx.x;
    if (i < Bn*Mn) g_cidx[i] = -1;
}

// ---------------- build projected embedding tables ----------------
// Et[t][d] = sum_p emb_t[t][p] * proj_w[d][C+p], etc.
__global__ void k_tables(const float* __restrict__ pw) {
    int row = blockIdx.x;    // 0..T+H+W-1
    __shared__ float emb[32];
    int pos, base;
    float* tab;
    if (row < Tn)           { pos = row;          base = Cn;        tab = g_Et + pos*Dn; }
    else if (row < Tn+Hn)   { pos = row - Tn;     base = Cn + Pn;   tab = g_Eh + pos*Dn; }
    else                    { pos = row - Tn - Hn; base = Cn + 2*Pn; tab = g_Ew + pos*Dn; }

    if (threadIdx.x < 32) {
        int p = threadIdx.x;
        int j = p & 15;
        double omega = pow(10000.0, -(double)j / 16.0);
        double a = (double)pos * omega;
        emb[p] = (p < 16) ? (float)sin(a) : (float)cos(a);
    }
    __syncthreads();

    for (int d = threadIdx.x; d < Dn; d += blockDim.x) {
        float acc = 0.0f;
        const float* wrow = pw + d*Fn + base;
        #pragma unroll
        for (int p = 0; p < 32; p++) acc += emb[p] * wrow[p];
        tab[d] = acc;
    }
}

// ---------------- pass A: per-chunk nonzero count ----------------
__global__ void k_count(const int* __restrict__ mask) {
    int b = blockIdx.y, c = blockIdx.x, tid = threadIdx.x;
    const int4* mk = (const int4*)(mask + (size_t)b*Nn + c*CHUNK);
    int cnt = 0;
    #pragma unroll
    for (int k = 0; k < 8; k++) {
        int4 v = mk[tid*8 + k];
        cnt += (v.x != 0) + (v.y != 0) + (v.z != 0) + (v.w != 0);
    }
    #pragma unroll
    for (int o = 16; o > 0; o >>= 1) cnt += __shfl_down_sync(0xffffffffu, cnt, o);
    __shared__ int s;
    if (tid == 0) s = 0;
    __syncthreads();
    if ((tid & 31) == 0) atomicAdd(&s, cnt);
    __syncthreads();
    if (tid == 0) g_chunk_cnt[b*NCHUNK + c] = s;
}

// ---------------- pass B: per-batch exclusive scan over chunks ----------------
__global__ void k_scan() {
    int b = threadIdx.x;
    if (b < Bn) {
        int r = 0;
        for (int c = 0; c < NCHUNK; c++) {
            g_chunk_off[b*NCHUNK + c] = r;
            r += g_chunk_cnt[b*NCHUNK + c];
        }
    }
}

// ---------------- pass C: stable scatter of voxel indices ----------------
__global__ void k_scatter(const int* __restrict__ mask) {
    int b = blockIdx.y, c = blockIdx.x, tid = threadIdx.x;
    const int4* mk = (const int4*)(mask + (size_t)b*Nn + c*CHUNK);
    int4 v[8];
    int cnt = 0;
    #pragma unroll
    for (int k = 0; k < 8; k++) {
        v[k] = mk[tid*8 + k];
        cnt += (v[k].x != 0) + (v[k].y != 0) + (v[k].z != 0) + (v[k].w != 0);
    }
    // inclusive warp scan
    int incl = cnt;
    #pragma unroll
    for (int o = 1; o < 32; o <<= 1) {
        int n = __shfl_up_sync(0xffffffffu, incl, o);
        if ((tid & 31) >= o) incl += n;
    }
    __shared__ int wsum[8];
    __shared__ int wbase[8];
    if ((tid & 31) == 31) wsum[tid >> 5] = incl;
    __syncthreads();
    if (tid == 0) {
        int r = 0;
        #pragma unroll
        for (int i = 0; i < 8; i++) { wbase[i] = r; r += wsum[i]; }
    }
    __syncthreads();
    int excl = wbase[tid >> 5] + incl - cnt;
    int r = g_chunk_off[b*NCHUNK + c] + excl;
    int vbase = c*CHUNK + tid*32;
    #pragma unroll
    for (int k = 0; k < 8; k++) {
        int e[4] = { v[k].x, v[k].y, v[k].z, v[k].w };
        #pragma unroll
        for (int j = 0; j < 4; j++) {
            if (e[j] != 0) {
                if (r < Mn) g_cidx[b*Mn + r] = vbase + k*4 + j;
                r++;
            }
        }
    }
}

// ---------------- pad mask output ----------------
__global__ void k_mask(float* __restrict__ out) {
    int i = blockIdx.x * blockDim.x + threadIdx.x;
    if (i < Bn*Mn) out[(size_t)Bn*Mn*Dn + i] = (g_cidx[i] < 0) ? 1.0f : 0.0f;
}

// ---------------- main fused gather + projected-table sum ----------------
__global__ void __launch_bounds__(512, 1) k_main(
    const float* __restrict__ y,
    const float* __restrict__ pw,
    const float* __restrict__ pb,
    float* __restrict__ out)
{
    extern __shared__ float s[];
    float* sEt = s;                   // Tn*DT
    float* sEh = s + Tn*DT;           // Hn*DT
    float* sEw = s + (Tn+Hn)*DT;      // Wn*DT

    int d0 = blockIdx.x * DT;
    int m0 = blockIdx.y * MT;
    int b  = blockIdx.z;
    int tid = threadIdx.x;

    for (int i = tid; i < Tn*DT; i += 512) sEt[i] = g_Et[(i >> 7)*Dn + d0 + (i & 127)];
    for (int i = tid; i < Hn*DT; i += 512) sEh[i] = g_Eh[(i >> 7)*Dn + d0 + (i & 127)];
    for (int i = tid; i < Wn*DT; i += 512) sEw[i] = g_Ew[(i >> 7)*Dn + d0 + (i & 127)];

    int col  = tid & 31;        // d-group within tile
    int rowp = tid >> 5;        // 0..15 : row lane
    int dl   = col * 4;
    int d    = d0 + dl;

    float w0[4], w1[4], bs[4];
    #pragma unroll
    for (int k = 0; k < 4; k++) {
        w0[k] = pw[(d + k)*Fn + 0];
        w1[k] = pw[(d + k)*Fn + 1];
        bs[k] = pb[d + k];
    }
    __syncthreads();

    const int*   cix = g_cidx + b*Mn;
    const float* y0  = y + (size_t)b*Cn*Nn;

    for (int m = m0 + rowp; m < m0 + MT; m += 16) {
        int vi = __ldg(cix + m);
        float4 o;
        if (vi >= 0) {
            int t = vi >> 14;
            int h = (vi >> 7) & 127;
            int w = vi & 127;
            float v0 = __ldg(y0 + vi);
            float v1 = __ldg(y0 + Nn + vi);
            float4 et = *(const float4*)&sEt[t*DT + dl];
            float4 eh = *(const float4*)&sEh[h*DT + dl];
            float4 ew = *(const float4*)&sEw[w*DT + dl];
            o.x = bs[0] + et.x + eh.x + ew.x + v0*w0[0] + v1*w1[0];
            o.y = bs[1] + et.y + eh.y + ew.y + v0*w0[1] + v1*w1[1];
            o.z = bs[2] + et.z + eh.z + ew.z + v0*w0[2] + v1*w1[2];
            o.w = bs[3] + et.w + eh.w + ew.w + v0*w0[3] + v1*w1[3];
        } else {
            o = make_float4(bs[0], bs[1], bs[2], bs[3]);
        }
        *(float4*)&out[((size_t)(b*Mn + m))*Dn + d] = o;
    }
}

extern "C" void kernel_launch(void* const* d_in, const int* in_sizes, int n_in,
                              void* d_out, int out_size) {
    const float* y    = (const float*)d_in[0];   // y_obs  (B,C,T,H,W)
    const int*   mask = (const int*)  d_in[1];   // mask1  (B,1,T,H,W)
    const float* pw   = (const float*)d_in[2];   // proj_w (D, F)
    const float* pb   = (const float*)d_in[3];   // proj_b (D,)
    float* out = (float*)d_out;

    k_init<<<(Bn*Mn + 1023) / 1024, 1024>>>();
    k_tables<<<Tn + Hn + Wn, 512>>>(pw);
    k_count<<<dim3(NCHUNK, Bn), 256>>>(mask);
    k_scan<<<1, 32>>>();
    k_scatter<<<dim3(NCHUNK, Bn), 256>>>(mask);

    if (out_size >= Bn*Mn*Dn + Bn*Mn)
        k_mask<<<(Bn*Mn + 1023) / 1024, 1024>>>(out);

    static bool attr_set = false;
    if (!attr_set) {
        cudaFuncSetAttribute(k_main, cudaFuncAttributeMaxDynamicSharedMemorySize, SMEM_MAIN);
        attr_set = true;
    }
    k_main<<<dim3(Dn/DT, Mn/MT, Bn), 512, SMEM_MAIN>>>(y, pw, pb, out);
}

// round 2
// speedup vs baseline: 1.9222x; 1.9222x over previous
#include <cuda_runtime.h>
#include <math.h>

#define Bn 4
#define Cn 2
#define Tn 8
#define Hn 128
#define Wn 128
#define Nn (Tn*Hn*Wn)        // 131072
#define Dn 512
#define Pn 32
#define Fn (Cn + 3*Pn)       // 98
#define Mn 65536

#define CHUNK 8192
#define NCHUNK (Nn/CHUNK)    // 16
#define DT 128               // d-tile
#define MT 2048              // m-tile
#define UN 8                 // m-unroll (independent record loads in flight)
#define SMEM_MAIN ((Tn+Hn+Wn)*DT*4)   // 135168 bytes

// scratch (no cudaMalloc allowed)
__device__ int    g_cidx[Bn*Mn];
__device__ int    g_chunk_cnt[Bn*NCHUNK];
__device__ int    g_chunk_off[Bn*NCHUNK];
__device__ int    g_cnt[Bn];
__device__ float4 g_rec[Bn*Mn];     // {v0, v1, vi_as_float_bits, 0}
__device__ float  g_Et[Tn*Dn];
__device__ float  g_Eh[Hn*Dn];
__device__ float  g_Ew[Wn*Dn];

// ---------------- build projected embedding tables ----------------
__global__ void k_tables(const float* __restrict__ pw) {
    int row = blockIdx.x;    // 0..T+H+W-1
    __shared__ float emb[32];
    int pos, base;
    float* tab;
    if (row < Tn)           { pos = row;           base = Cn;         tab = g_Et + pos*Dn; }
    else if (row < Tn+Hn)   { pos = row - Tn;      base = Cn + Pn;    tab = g_Eh + pos*Dn; }
    else                    { pos = row - Tn - Hn; base = Cn + 2*Pn;  tab = g_Ew + pos*Dn; }

    if (threadIdx.x < 32) {
        int p = threadIdx.x;
        int j = p & 15;
        double omega = pow(10000.0, -(double)j / 16.0);
        double a = (double)pos * omega;
        emb[p] = (p < 16) ? (float)sin(a) : (float)cos(a);
    }
    __syncthreads();

    for (int d = threadIdx.x; d < Dn; d += blockDim.x) {
        float acc = 0.0f;
        const float* wrow = pw + d*Fn + base;
        #pragma unroll
        for (int p = 0; p < 32; p++) acc += emb[p] * wrow[p];
        tab[d] = acc;
    }
}

// ---------------- pass A: per-chunk nonzero count ----------------
__global__ void k_count(const int* __restrict__ mask) {
    int b = blockIdx.y, c = blockIdx.x, tid = threadIdx.x;
    const int4* mk = (const int4*)(mask + (size_t)b*Nn + c*CHUNK);
    int cnt = 0;
    #pragma unroll
    for (int k = 0; k < 8; k++) {
        int4 v = mk[tid*8 + k];
        cnt += (v.x != 0) + (v.y != 0) + (v.z != 0) + (v.w != 0);
    }
    #pragma unroll
    for (int o = 16; o > 0; o >>= 1) cnt += __shfl_down_sync(0xffffffffu, cnt, o);
    __shared__ int s;
    if (tid == 0) s = 0;
    __syncthreads();
    if ((tid & 31) == 0) atomicAdd(&s, cnt);
    __syncthreads();
    if (tid == 0) g_chunk_cnt[b*NCHUNK + c] = s;
}

// ---------------- pass B: per-batch exclusive scan over chunks ----------------
__global__ void k_scan() {
    int b = threadIdx.x;
    if (b < Bn) {
        int r = 0;
        for (int c = 0; c < NCHUNK; c++) {
            g_chunk_off[b*NCHUNK + c] = r;
            r += g_chunk_cnt[b*NCHUNK + c];
        }
        g_cnt[b] = (r < Mn) ? r : Mn;
    }
}

// ---------------- pass C: stable scatter of voxel indices ----------------
__global__ void k_scatter(const int* __restrict__ mask) {
    int b = blockIdx.y, c = blockIdx.x, tid = threadIdx.x;
    const int4* mk = (const int4*)(mask + (size_t)b*Nn + c*CHUNK);
    int4 v[8];
    int cnt = 0;
    #pragma unroll
    for (int k = 0; k < 8; k++) {
        v[k] = mk[tid*8 + k];
        cnt += (v[k].x != 0) + (v[k].y != 0) + (v[k].z != 0) + (v[k].w != 0);
    }
    int incl = cnt;
    #pragma unroll
    for (int o = 1; o < 32; o <<= 1) {
        int n = __shfl_up_sync(0xffffffffu, incl, o);
        if ((tid & 31) >= o) incl += n;
    }
    __shared__ int wsum[8];
    __shared__ int wbase[8];
    if ((tid & 31) == 31) wsum[tid >> 5] = incl;
    __syncthreads();
    if (tid == 0) {
        int r = 0;
        #pragma unroll
        for (int i = 0; i < 8; i++) { wbase[i] = r; r += wsum[i]; }
    }
    __syncthreads();
    int excl = wbase[tid >> 5] + incl - cnt;
    int r = g_chunk_off[b*NCHUNK + c] + excl;
    int vbase = c*CHUNK + tid*32;
    #pragma unroll
    for (int k = 0; k < 8; k++) {
        int e[4] = { v[k].x, v[k].y, v[k].z, v[k].w };
        #pragma unroll
        for (int j = 0; j < 4; j++) {
            if (e[j] != 0) {
                if (r < Mn) g_cidx[b*Mn + r] = vbase + k*4 + j;
                r++;
            }
        }
    }
}

// ---------------- pack per-token records + pad mask ----------------
__global__ void k_pack(const float* __restrict__ y, float* __restrict__ out) {
    int i = blockIdx.x * blockDim.x + threadIdx.x;   // 0..Bn*Mn-1
    int b = i >> 16;
    int m = i & (Mn - 1);
    bool valid = m < g_cnt[b];
    float4 r;
    if (valid) {
        int vi = g_cidx[i];
        const float* y0 = y + (size_t)b*Cn*Nn;
        r.x = __ldg(y0 + vi);
        r.y = __ldg(y0 + Nn + vi);
        r.z = __int_as_float(vi);
    } else {
        r.x = 0.0f; r.y = 0.0f; r.z = __int_as_float(-1);
    }
    r.w = 0.0f;
    g_rec[i] = r;
    out[(size_t)Bn*Mn*Dn + i] = valid ? 0.0f : 1.0f;
}

// ---------------- main: streaming projected-table sum ----------------
__global__ void __launch_bounds__(512, 1) k_main(
    const float* __restrict__ pw,
    const float* __restrict__ pb,
    float* __restrict__ out)
{
    extern __shared__ float s[];
    float* sEt = s;                   // Tn*DT
    float* sEh = s + Tn*DT;           // Hn*DT
    float* sEw = s + (Tn+Hn)*DT;      // Wn*DT

    int d0 = blockIdx.x * DT;
    int m0 = blockIdx.y * MT;
    int b  = blockIdx.z;
    int tid = threadIdx.x;

    for (int i = tid; i < Tn*DT; i += 512) sEt[i] = g_Et[(i >> 7)*Dn + d0 + (i & 127)];
    for (int i = tid; i < Hn*DT; i += 512) sEh[i] = g_Eh[(i >> 7)*Dn + d0 + (i & 127)];
    for (int i = tid; i < Wn*DT; i += 512) sEw[i] = g_Ew[(i >> 7)*Dn + d0 + (i & 127)];

    int col  = tid & 31;        // d-group within tile
    int rowp = tid >> 5;        // 0..15 : m lane
    int dl   = col * 4;
    int d    = d0 + dl;

    float w0[4], w1[4], bs[4];
    #pragma unroll
    for (int k = 0; k < 4; k++) {
        w0[k] = pw[(d + k)*Fn + 0];
        w1[k] = pw[(d + k)*Fn + 1];
        bs[k] = pb[d + k];
    }
    __syncthreads();

    const float4* rec = g_rec + b*Mn;
    float* ob = out + ((size_t)b*Mn)*Dn + d;

    #pragma unroll 1
    for (int m = m0 + rowp; m < m0 + MT; m += 16*UN) {
        float4 r[UN];
        #pragma unroll
        for (int j = 0; j < UN; j++) r[j] = __ldg(rec + m + j*16);

        #pragma unroll
        for (int j = 0; j < UN; j++) {
            int vi = __float_as_int(r[j].z);
            float4 o;
            if (vi >= 0) {
                int t = vi >> 14;
                int h = (vi >> 7) & 127;
                int w = vi & 127;
                float4 et = *(const float4*)&sEt[t*DT + dl];
                float4 eh = *(const float4*)&sEh[h*DT + dl];
                float4 ew = *(const float4*)&sEw[w*DT + dl];
                o.x = bs[0] + et.x + eh.x + ew.x + r[j].x*w0[0] + r[j].y*w1[0];
                o.y = bs[1] + et.y + eh.y + ew.y + r[j].x*w0[1] + r[j].y*w1[1];
                o.z = bs[2] + et.z + eh.z + ew.z + r[j].x*w0[2] + r[j].y*w1[2];
                o.w = bs[3] + et.w + eh.w + ew.w + r[j].x*w0[3] + r[j].y*w1[3];
            } else {
                o = make_float4(bs[0], bs[1], bs[2], bs[3]);
            }
            *(float4*)&ob[(size_t)(m + j*16)*Dn] = o;
        }
    }
}

extern "C" void kernel_launch(void* const* d_in, const int* in_sizes, int n_in,
                              void* d_out, int out_size) {
    const float* y    = (const float*)d_in[0];   // y_obs  (B,C,T,H,W)
    const int*   mask = (const int*)  d_in[1];   // mask1  (B,1,T,H,W)
    const float* pw   = (const float*)d_in[2];   // proj_w (D, F)
    const float* pb   = (const float*)d_in[3];   // proj_b (D,)
    float* out = (float*)d_out;

    k_tables<<<Tn + Hn + Wn, 512>>>(pw);                 // launch 0
    k_count<<<dim3(NCHUNK, Bn), 256>>>(mask);            // launch 1
    k_scan<<<1, 32>>>();                                 // launch 2
    k_scatter<<<dim3(NCHUNK, Bn), 256>>>(mask);          // launch 3
    k_pack<<<(Bn*Mn) / 256, 256>>>(y, out);              // launch 4

    static bool attr_set = false;
    if (!attr_set) {
        cudaFuncSetAttribute(k_main, cudaFuncAttributeMaxDynamicSharedMemorySize, SMEM_MAIN);
        attr_set = true;
    }
    k_main<<<dim3(Dn/DT, Mn/MT, Bn), 512, SMEM_MAIN>>>(pw, pb, out);  // launch 5 (ncu -s 5 captures this)
}

// round 3
// speedup vs baseline: 2.3191x; 1.2065x over previous
#include <cuda_runtime.h>
#include <math.h>

#define Bn 4
#define Cn 2
#define Tn 8
#define Hn 128
#define Wn 128
#define Nn (Tn*Hn*Wn)        // 131072
#define Dn 512
#define Pn 32
#define Fn (Cn + 3*Pn)       // 98
#define Mn 65536

#define CHUNK 8192
#define NCHUNK (Nn/CHUNK)    // 16
#define DT 128               // d-tile
#define MT 2048              // m-tile
#define UN 4                 // m-unroll (independent record loads in flight)
#define SMEM_MAIN ((Tn+Hn+Wn)*DT*4)   // 135168 bytes

// scratch (no cudaMalloc allowed)
__device__ int    g_pref[Bn*NCHUNK];   // lookback: (inclusive prefix)+1, 0 = not ready
__device__ int    g_cnt[Bn];
__device__ float4 g_rec[Bn*Mn];        // {v0, v1, vi_as_float_bits, 0} for m < cnt[b]
__device__ float  g_Et[Tn*Dn];
__device__ float  g_Eh[Hn*Dn];
__device__ float  g_Ew[Wn*Dn];

// ---------------- build projected embedding tables (+ reset lookback flags) ----------------
__global__ void k_tables(const float* __restrict__ pw) {
    if (blockIdx.x == 0 && threadIdx.x < Bn*NCHUNK) g_pref[threadIdx.x] = 0;

    int row = blockIdx.x;    // 0..T+H+W-1
    __shared__ float emb[32];
    int pos, base;
    float* tab;
    if (row < Tn)           { pos = row;           base = Cn;         tab = g_Et + pos*Dn; }
    else if (row < Tn+Hn)   { pos = row - Tn;      base = Cn + Pn;    tab = g_Eh + pos*Dn; }
    else                    { pos = row - Tn - Hn; base = Cn + 2*Pn;  tab = g_Ew + pos*Dn; }

    if (threadIdx.x < 32) {
        int p = threadIdx.x;
        int j = p & 15;
        double omega = pow(10000.0, -(double)j / 16.0);
        double a = (double)pos * omega;
        emb[p] = (p < 16) ? (float)sin(a) : (float)cos(a);
    }
    __syncthreads();

    for (int d = threadIdx.x; d < Dn; d += blockDim.x) {
        float acc = 0.0f;
        const float* wrow = pw + d*Fn + base;
        #pragma unroll
        for (int p = 0; p < 32; p++) acc += emb[p] * wrow[p];
        tab[d] = acc;
    }
}

// ---------------- fused compact: count + lookback scan + scatter + value gather ----------------
__global__ void __launch_bounds__(256) k_compact(const int* __restrict__ mask,
                                                 const float* __restrict__ y) {
    int b = blockIdx.y, c = blockIdx.x, tid = threadIdx.x;
    const int4* mk = (const int4*)(mask + (size_t)b*Nn + c*CHUNK);

    int4 v[8];
    int cnt = 0;
    #pragma unroll
    for (int k = 0; k < 8; k++) {
        v[k] = mk[tid*8 + k];
        cnt += (v[k].x != 0) + (v[k].y != 0) + (v[k].z != 0) + (v[k].w != 0);
    }
    // inclusive warp scan of per-thread counts
    int incl = cnt;
    #pragma unroll
    for (int o = 1; o < 32; o <<= 1) {
        int n = __shfl_up_sync(0xffffffffu, incl, o);
        if ((tid & 31) >= o) incl += n;
    }
    __shared__ int wsum[8];
    __shared__ int wbase[8];
    __shared__ int sbase;
    if ((tid & 31) == 31) wsum[tid >> 5] = incl;
    __syncthreads();

    if (tid == 0) {
        int r = 0;
        #pragma unroll
        for (int i = 0; i < 8; i++) { wbase[i] = r; r += wsum[i]; }
        int total = r;
        // decoupled chaining on previous chunk's inclusive prefix
        int prev = 0;
        if (c > 0) {
            int p;
            while ((p = atomicAdd(&g_pref[b*NCHUNK + c - 1], 0)) == 0) { }
            prev = p - 1;
        }
        int my_incl = prev + total;
        atomicExch(&g_pref[b*NCHUNK + c], my_incl + 1);
        if (c == NCHUNK - 1) g_cnt[b] = (my_incl < Mn) ? my_incl : Mn;
        sbase = prev;
    }
    __syncthreads();

    int r = sbase + wbase[tid >> 5] + incl - cnt;   // global exclusive offset
    int vbase = c*CHUNK + tid*32;
    const float* y0 = y + (size_t)b*Cn*Nn;
    float4* rec = g_rec + b*Mn;
    #pragma unroll
    for (int k = 0; k < 8; k++) {
        int e[4] = { v[k].x, v[k].y, v[k].z, v[k].w };
        #pragma unroll
        for (int j = 0; j < 4; j++) {
            if (e[j] != 0) {
                if (r < Mn) {
                    int vi = vbase + k*4 + j;
                    float4 rr;
                    rr.x = __ldg(y0 + vi);
                    rr.y = __ldg(y0 + Nn + vi);
                    rr.z = __int_as_float(vi);
                    rr.w = 0.0f;
                    rec[r] = rr;
                }
                r++;
            }
        }
    }
}

// ---------------- main: streaming projected-table sum + pad mask ----------------
__global__ void __launch_bounds__(1024, 1) k_main(
    const float* __restrict__ pw,
    const float* __restrict__ pb,
    float* __restrict__ out)
{
    extern __shared__ float s[];
    float* sEt = s;                   // Tn*DT
    float* sEh = s + Tn*DT;           // Hn*DT
    float* sEw = s + (Tn+Hn)*DT;      // Wn*DT

    int d0 = blockIdx.x * DT;
    int m0 = blockIdx.y * MT;
    int b  = blockIdx.z;
    int tid = threadIdx.x;

    int cnt = g_cnt[b];

    // pad mask (one d-tile column of blocks handles it)
    if (blockIdx.x == 0) {
        for (int i = tid; i < MT; i += 1024) {
            int m = m0 + i;
            out[(size_t)Bn*Mn*Dn + b*Mn + m] = (m < cnt) ? 0.0f : 1.0f;
        }
    }

    // vectorized table fills (DT=128 floats per row -> 32 float4)
    for (int i = tid; i < Tn*(DT/4); i += 1024) {
        int row = i >> 5, c4 = i & 31;
        ((float4*)sEt)[i] = *(const float4*)&g_Et[row*Dn + d0 + c4*4];
    }
    for (int i = tid; i < Hn*(DT/4); i += 1024) {
        int row = i >> 5, c4 = i & 31;
        ((float4*)sEh)[i] = *(const float4*)&g_Eh[row*Dn + d0 + c4*4];
        ((float4*)sEw)[i] = *(const float4*)&g_Ew[row*Dn + d0 + c4*4];
    }

    int col  = tid & 31;        // d-group within tile
    int rowp = tid >> 5;        // 0..31 : m lane
    int dl   = col * 4;
    int d    = d0 + dl;

    float w0[4], w1[4], bs[4];
    #pragma unroll
    for (int k = 0; k < 4; k++) {
        w0[k] = pw[(d + k)*Fn + 0];
        w1[k] = pw[(d + k)*Fn + 1];
        bs[k] = pb[d + k];
    }
    __syncthreads();

    const float4* rec = g_rec + b*Mn;
    float* ob = out + ((size_t)b*Mn)*Dn + d;

    #pragma unroll 1
    for (int mb = m0 + rowp; mb < m0 + MT; mb += 32*UN) {
        float4 r[UN];
        #pragma unroll
        for (int j = 0; j < UN; j++) r[j] = __ldg(rec + mb + j*32);

        #pragma unroll
        for (int j = 0; j < UN; j++) {
            int m = mb + j*32;
            float4 o = make_float4(bs[0], bs[1], bs[2], bs[3]);
            if (m < cnt) {
                int vi = __float_as_int(r[j].z);
                int t = (vi >> 14) & 7;
                int h = (vi >> 7) & 127;
                int w = vi & 127;
                float4 et = *(const float4*)&sEt[t*DT + dl];
                float4 eh = *(const float4*)&sEh[h*DT + dl];
                float4 ew = *(const float4*)&sEw[w*DT + dl];
                o.x += et.x + eh.x + ew.x + r[j].x*w0[0] + r[j].y*w1[0];
                o.y += et.y + eh.y + ew.y + r[j].x*w0[1] + r[j].y*w1[1];
                o.z += et.z + eh.z + ew.z + r[j].x*w0[2] + r[j].y*w1[2];
                o.w += et.w + eh.w + ew.w + r[j].x*w0[3] + r[j].y*w1[3];
            }
            *(float4*)&ob[(size_t)m*Dn] = o;
        }
    }
}

extern "C" void kernel_launch(void* const* d_in, const int* in_sizes, int n_in,
                              void* d_out, int out_size) {
    const float* y    = (const float*)d_in[0];   // y_obs  (B,C,T,H,W)
    const int*   mask = (const int*)  d_in[1];   // mask1  (B,1,T,H,W)
    const float* pw   = (const float*)d_in[2];   // proj_w (D, F)
    const float* pb   = (const float*)d_in[3];   // proj_b (D,)
    float* out = (float*)d_out;

    k_tables<<<Tn + Hn + Wn, 512>>>(pw);               // launch 0 (also resets lookback flags)
    k_compact<<<dim3(NCHUNK, Bn), 256>>>(mask, y);     // launch 1

    static bool attr_set = false;
    if (!attr_set) {
        cudaFuncSetAttribute(k_main, cudaFuncAttributeMaxDynamicSharedMemorySize, SMEM_MAIN);
        attr_set = true;
    }
    k_main<<<dim3(Dn/DT, Mn/MT, Bn), 1024, SMEM_MAIN>>>(pw, pb, out);  // launch 2
}

// round 4
// speedup vs baseline: 3.3087x; 1.4267x over previous
#include <cuda_runtime.h>
#include <math.h>

#define Bn 4
#define Cn 2
#define Tn 8
#define Hn 128
#define Wn 128
#define Nn (Tn*Hn*Wn)        // 131072
#define Dn 512
#define Pn 32
#define Fn (Cn + 3*Pn)       // 98
#define Mn 65536

#define CHUNK 8192
#define NCHUNK (Nn/CHUNK)    // 16
#define NCOMPACT (NCHUNK*Bn) // 64 compact blocks
#define DT 128               // d-tile
#define MT 512               // m-tile (persistent)
#define UN 4                 // m-unroll
#define NSM 148
#define NDG 4                // d-groups (512/128)
#define JGN (NSM/NDG)        // 37 blocks per d-group
#define SMEM_MAIN ((Tn+Hn+Wn)*DT*4)   // 135168 bytes

// scratch (no cudaMalloc allowed; zero-initialized at load)
__device__ int    g_pref[Bn*NCHUNK];   // lookback: (inclusive prefix)+1, 0 = not ready (self-resetting)
__device__ int    g_cnt[Bn];
__device__ float4 g_rec[Bn*Mn];        // {v0, v1, vi_as_float_bits, 0} for m < cnt[b]
__device__ float  g_Et[Tn*Dn];
__device__ float  g_Eh[Hn*Dn];
__device__ float  g_Ew[Wn*Dn];

// ---------------- fused: compact (blocks 0..63) + projected tables (blocks 64..327) ----------------
__global__ void __launch_bounds__(256) k_fused(const int* __restrict__ mask,
                                               const float* __restrict__ y,
                                               const float* __restrict__ pw) {
    int tid = threadIdx.x;

    if (blockIdx.x < NCOMPACT) {
        // ---- compact role: count + decoupled lookback + scatter + value gather ----
        int b = blockIdx.x >> 4;
        int c = blockIdx.x & 15;
        const int4* mk = (const int4*)(mask + (size_t)b*Nn + c*CHUNK);

        int4 v[8];
        int cnt = 0;
        #pragma unroll
        for (int k = 0; k < 8; k++) {
            v[k] = mk[tid*8 + k];
            cnt += (v[k].x != 0) + (v[k].y != 0) + (v[k].z != 0) + (v[k].w != 0);
        }
        int incl = cnt;
        #pragma unroll
        for (int o = 1; o < 32; o <<= 1) {
            int n = __shfl_up_sync(0xffffffffu, incl, o);
            if ((tid & 31) >= o) incl += n;
        }
        __shared__ int wsum[8];
        __shared__ int wbase[8];
        __shared__ int sbase;
        if ((tid & 31) == 31) wsum[tid >> 5] = incl;
        __syncthreads();

        if (tid == 0) {
            int r = 0;
            #pragma unroll
            for (int i = 0; i < 8; i++) { wbase[i] = r; r += wsum[i]; }
            int total = r;
            int prev = 0;
            if (c > 0) {
                int p;
                while ((p = atomicAdd(&g_pref[b*NCHUNK + c - 1], 0)) == 0) { }
                prev = p - 1;
                atomicExch(&g_pref[b*NCHUNK + c - 1], 0);   // self-reset for next replay
            }
            int my_incl = prev + total;
            if (c == NCHUNK - 1) g_cnt[b] = (my_incl < Mn) ? my_incl : Mn;
            else                 atomicExch(&g_pref[b*NCHUNK + c], my_incl + 1);
            sbase = prev;
        }
        __syncthreads();

        int r = sbase + wbase[tid >> 5] + incl - cnt;
        int vbase = c*CHUNK + tid*32;
        const float* y0 = y + (size_t)b*Cn*Nn;
        float4* rec = g_rec + b*Mn;
        #pragma unroll
        for (int k = 0; k < 8; k++) {
            int e[4] = { v[k].x, v[k].y, v[k].z, v[k].w };
            #pragma unroll
            for (int j = 0; j < 4; j++) {
                if (e[j] != 0) {
                    if (r < Mn) {
                        int vi = vbase + k*4 + j;
                        float4 rr;
                        rr.x = __ldg(y0 + vi);
                        rr.y = __ldg(y0 + Nn + vi);
                        rr.z = __int_as_float(vi);
                        rr.w = 0.0f;
                        rec[r] = rr;
                    }
                    r++;
                }
            }
        }
    } else {
        // ---- table role: Etab[pos][d] = sum_p emb[pos][p] * pw[d][base+p] ----
        int row = blockIdx.x - NCOMPACT;   // 0..263
        __shared__ float emb[32];
        int pos, base;
        float* tab;
        if (row < Tn)           { pos = row;           base = Cn;         tab = g_Et + pos*Dn; }
        else if (row < Tn+Hn)   { pos = row - Tn;      base = Cn + Pn;    tab = g_Eh + pos*Dn; }
        else                    { pos = row - Tn - Hn; base = Cn + 2*Pn;  tab = g_Ew + pos*Dn; }

        if (tid < 16) {
            float omega = exp2f(-(float)tid * (13.287712379549449f / 16.0f));  // 10000^(-j/16)
            float a = (float)pos * omega;
            float s, cth;
            sincosf(a, &s, &cth);
            emb[tid] = s;
            emb[tid + 16] = cth;
        }
        __syncthreads();

        for (int d = tid; d < Dn; d += 256) {
            float acc = 0.0f;
            const float* wrow = pw + d*Fn + base;
            #pragma unroll
            for (int p = 0; p < 32; p++) acc += emb[p] * wrow[p];
            tab[d] = acc;
        }
    }
}

// ---------------- main: persistent streaming projected-table sum + pad mask ----------------
__global__ void __launch_bounds__(1024, 1) k_main(
    const float* __restrict__ pw,
    const float* __restrict__ pb,
    float* __restrict__ out)
{
    extern __shared__ float s[];
    float* sEt = s;                   // Tn*DT
    float* sEh = s + Tn*DT;           // Hn*DT
    float* sEw = s + (Tn+Hn)*DT;      // Wn*DT

    int g  = blockIdx.x & (NDG - 1);   // d-group
    int jg = blockIdx.x >> 2;          // 0..36
    int d0 = g * DT;
    int tid = threadIdx.x;

    // one-time table fill for this block's fixed d-tile
    for (int i = tid; i < Tn*(DT/4); i += 1024) {
        int row = i >> 5, c4 = i & 31;
        ((float4*)sEt)[i] = *(const float4*)&g_Et[row*Dn + d0 + c4*4];
    }
    for (int i = tid; i < Hn*(DT/4); i += 1024) {
        int row = i >> 5, c4 = i & 31;
        ((float4*)sEh)[i] = *(const float4*)&g_Eh[row*Dn + d0 + c4*4];
        ((float4*)sEw)[i] = *(const float4*)&g_Ew[row*Dn + d0 + c4*4];
    }

    int col  = tid & 31;        // d-group lane
    int rowp = tid >> 5;        // 0..31 : m lane
    int dl   = col * 4;
    int d    = d0 + dl;

    float w0[4], w1[4], bs[4];
    #pragma unroll
    for (int k = 0; k < 4; k++) {
        w0[k] = pw[(d + k)*Fn + 0];
        w1[k] = pw[(d + k)*Fn + 1];
        bs[k] = pb[d + k];
    }
    __syncthreads();

    const int TILES = Bn * (Mn / MT);   // 512

    for (int tile = jg; tile < TILES; tile += JGN) {
        int b  = tile >> 7;             // tile / 128
        int m0 = (tile & 127) * MT;
        int cnt = __ldg(&g_cnt[b]);

        if (g == 0 && tid < MT) {
            int m = m0 + tid;
            out[(size_t)Bn*Mn*Dn + b*Mn + m] = (m < cnt) ? 0.0f : 1.0f;
        }

        const float4* rec = g_rec + b*Mn;
        float* ob = out + ((size_t)b*Mn + m0)*Dn + d;

        #pragma unroll 1
        for (int mo = rowp; mo < MT; mo += 32*UN) {
            float4 r[UN];
            #pragma unroll
            for (int j = 0; j < UN; j++) r[j] = __ldg(rec + m0 + mo + j*32);

            #pragma unroll
            for (int j = 0; j < UN; j++) {
                int m = m0 + mo + j*32;
                float4 o = make_float4(bs[0], bs[1], bs[2], bs[3]);
                if (m < cnt) {
                    int vi = __float_as_int(r[j].z);
                    int t = (vi >> 14) & 7;
                    int h = (vi >> 7) & 127;
                    int w = vi & 127;
                    float4 et = *(const float4*)&sEt[t*DT + dl];
                    float4 eh = *(const float4*)&sEh[h*DT + dl];
                    float4 ew = *(const float4*)&sEw[w*DT + dl];
                    o.x += et.x + eh.x + ew.x + r[j].x*w0[0] + r[j].y*w1[0];
                    o.y += et.y + eh.y + ew.y + r[j].x*w0[1] + r[j].y*w1[1];
                    o.z += et.z + eh.z + ew.z + r[j].x*w0[2] + r[j].y*w1[2];
                    o.w += et.w + eh.w + ew.w + r[j].x*w0[3] + r[j].y*w1[3];
                }
                __stcs((float4*)&ob[(size_t)(mo + j*32)*Dn], o);
            }
        }
    }
}

extern "C" void kernel_launch(void* const* d_in, const int* in_sizes, int n_in,
                              void* d_out, int out_size) {
    const float* y    = (const float*)d_in[0];   // y_obs  (B,C,T,H,W)
    const int*   mask = (const int*)  d_in[1];   // mask1  (B,1,T,H,W)
    const float* pw   = (const float*)d_in[2];   // proj_w (D, F)
    const float* pb   = (const float*)d_in[3];   // proj_b (D,)
    float* out = (float*)d_out;

    k_fused<<<NCOMPACT + Tn + Hn + Wn, 256>>>(mask, y, pw);   // launch 0

    static bool attr_set = false;
    if (!attr_set) {
        cudaFuncSetAttribute(k_main, cudaFuncAttributeMaxDynamicSharedMemorySize, SMEM_MAIN);
        attr_set = true;
    }
    k_main<<<NSM, 1024, SMEM_MAIN>>>(pw, pb, out);            // launch 1 (ncu -s 5 -> this, replay 3)
}